// round 10
// baseline (speedup 1.0000x reference)
#include <cuda_runtime.h>
#include <cuda_bf16.h>
#include <cstdint>

// ===========================================================================
// PQLinear: out = x @ wq.T + bias (wq = PQ-dequantized weight).
//  K1: pq_quant (scalar fp32 argmin, byte-identical math to R5/R7/R9)
//      -> wh bf16, plus fp8 pair (wh/16, wl*16)  [wl = exact fp32 residual]
//  K2: xsplit -> xh bf16, plus fp8 pair (xh/16, xl*16)
//  K3: one GEMM: 32 bf16 k-tiles (xh*wh) + 16 fp8 k-tiles (xh/16 * wl*16)
//      + 16 fp8 k-tiles (xl*16 * wh/16). fp8 mma m16n8k32 does 2x K/instr;
//      byte-level fragment layout identical to bf16 k16 -> same ldmatrix.
// ===========================================================================

#define ODIM 2048
#define IDIM 2048
#define MDIM 4096
#define KCB  256
#define NGROUPS ((ODIM * IDIM) / 8)     // 524288
#define GPR_SHIFT 8                     // groups per weight row

__device__ __align__(16) __nv_bfloat16 g_wh[ODIM * IDIM];
__device__ __align__(16) __nv_bfloat16 g_xh[MDIM * IDIM];
__device__ __align__(16) uint8_t g_wh8[ODIM * IDIM];   // e4m3(wh / 16)
__device__ __align__(16) uint8_t g_wl8[ODIM * IDIM];   // e4m3(wl * 16)
__device__ __align__(16) uint8_t g_xh8[MDIM * IDIM];   // e4m3(xh / 16)
__device__ __align__(16) uint8_t g_xl8[MDIM * IDIM];   // e4m3(xl * 16)

// cvt.rn.satfinite.e4m3x2.f32 d, a, b  ->  d[15:8]=e4m3(a), d[7:0]=e4m3(b)
__device__ __forceinline__ uint16_t cvt_e4m3x2(float hi, float lo) {
    uint16_t r;
    asm("cvt.rn.satfinite.e4m3x2.f32 %0, %1, %2;" : "=h"(r) : "f"(hi), "f"(lo));
    return r;
}

// ===========================================================================
// Kernel 1: PQ quantize (argmin math byte-identical to verified kernel).
// ===========================================================================
__global__ __launch_bounds__(256)
void pq_quant_kernel(const float* __restrict__ w,
                     const float* __restrict__ cb,
                     const float* __restrict__ rs) {
    __shared__ float4 s_cb[KCB * 2];
    __shared__ float  s_cn[KCB];

    const int tid = threadIdx.x;
    const float4* cb4 = reinterpret_cast<const float4*>(cb);
    for (int i = tid; i < KCB * 2; i += 256) s_cb[i] = cb4[i];
    __syncthreads();
    for (int i = tid; i < KCB; i += 256) {
        float4 a = s_cb[2 * i], b = s_cb[2 * i + 1];
        s_cn[i] = a.x * a.x + a.y * a.y + a.z * a.z + a.w * a.w +
                  b.x * b.x + b.y * b.y + b.z * b.z + b.w * b.w;
    }
    __syncthreads();

    const int g = blockIdx.x * 256 + tid;
    const int row = g >> GPR_SHIFT;
    const float scale = rs[row];

    const float4* w4 = reinterpret_cast<const float4*>(w);
    float4 w0 = w4[2 * g], w1 = w4[2 * g + 1];
    float gv0 = w0.x / scale, gv1 = w0.y / scale, gv2 = w0.z / scale, gv3 = w0.w / scale;
    float gv4 = w1.x / scale, gv5 = w1.y / scale, gv6 = w1.z / scale, gv7 = w1.w / scale;

    float best = 3.402823466e38f;
    int bi = 0;
#pragma unroll 8
    for (int k = 0; k < KCB; ++k) {
        float4 c0 = s_cb[2 * k], c1 = s_cb[2 * k + 1];
        float dot = gv0 * c0.x;
        dot = fmaf(gv1, c0.y, dot);
        dot = fmaf(gv2, c0.z, dot);
        dot = fmaf(gv3, c0.w, dot);
        dot = fmaf(gv4, c1.x, dot);
        dot = fmaf(gv5, c1.y, dot);
        dot = fmaf(gv6, c1.z, dot);
        dot = fmaf(gv7, c1.w, dot);
        float d = fmaf(-2.0f, dot, s_cn[k]);
        if (d < best) { best = d; bi = k; }       // strict <: first index wins
    }

    float4 q0 = s_cb[2 * bi], q1 = s_cb[2 * bi + 1];
    float vals[8] = {q0.x * scale, q0.y * scale, q0.z * scale, q0.w * scale,
                     q1.x * scale, q1.y * scale, q1.z * scale, q1.w * scale};

    union B8 { __nv_bfloat16 b[8]; uint4 u; } hh;
    float hf[8], lf[8];
#pragma unroll
    for (int j = 0; j < 8; ++j) {
        __nv_bfloat16 h = __float2bfloat16(vals[j]);
        hh.b[j] = h;
        hf[j] = __bfloat162float(h);
        lf[j] = vals[j] - hf[j];                  // exact fp32 residual
    }
    reinterpret_cast<uint4*>(g_wh)[g] = hh.u;

    union P8 { uint16_t h[4]; unsigned long long u; } ph, pl;
#pragma unroll
    for (int j = 0; j < 4; ++j) {
        ph.h[j] = cvt_e4m3x2(hf[2 * j + 1] * 0.0625f, hf[2 * j] * 0.0625f);
        pl.h[j] = cvt_e4m3x2(lf[2 * j + 1] * 16.0f,   lf[2 * j] * 16.0f);
    }
    reinterpret_cast<unsigned long long*>(g_wh8)[g] = ph.u;
    reinterpret_cast<unsigned long long*>(g_wl8)[g] = pl.u;
}

// ===========================================================================
// Kernel 2: split x -> xh bf16 + fp8 pair (xh/16, xl*16).
// ===========================================================================
__global__ __launch_bounds__(256)
void xsplit_kernel(const float* __restrict__ x) {
    const int i = blockIdx.x * 256 + threadIdx.x;     // float4 index
    float4 v = reinterpret_cast<const float4*>(x)[i];
    float vs[4] = {v.x, v.y, v.z, v.w};
    union B4 { __nv_bfloat16 b[4]; uint2 u; } hh;
    float hf[4], lf[4];
#pragma unroll
    for (int j = 0; j < 4; ++j) {
        __nv_bfloat16 h = __float2bfloat16(vs[j]);
        hh.b[j] = h;
        hf[j] = __bfloat162float(h);
        lf[j] = vs[j] - hf[j];
    }
    reinterpret_cast<uint2*>(g_xh)[i] = hh.u;

    union P4 { uint16_t h[2]; uint32_t u; } ph, pl;
#pragma unroll
    for (int j = 0; j < 2; ++j) {
        ph.h[j] = cvt_e4m3x2(hf[2 * j + 1] * 0.0625f, hf[2 * j] * 0.0625f);
        pl.h[j] = cvt_e4m3x2(lf[2 * j + 1] * 16.0f,   lf[2 * j] * 16.0f);
    }
    reinterpret_cast<uint32_t*>(g_xh8)[i] = ph.u;
    reinterpret_cast<uint32_t*>(g_xl8)[i] = pl.u;
}

// ===========================================================================
// Kernel 3: mixed bf16/fp8 mma.sync GEMM.
//   kt  0..31: bf16  xh * wh          (BK=64  bf16 = 128 B rows)
//   kt 32..47: e4m3 (xh/16)*(wl*16)   (BK=128 fp8  = 128 B rows)
//   kt 48..63: e4m3 (xl*16)*(wh/16)
// BM=BN=128, 128 threads (4 warps, 64x64 warp tiles), 3-stage cp.async.
// ===========================================================================
#define BM 128
#define BN 128
#define NST 3
#define KTOT 64
#define GTHREADS 128
#define TILE_A_BYTES (BM * 128)        // 16 KB (128 bytes per row)
#define TILE_B_BYTES (BN * 128)
#define STAGE_BYTES (TILE_A_BYTES + TILE_B_BYTES)   // 32 KB
#define GEMM_SMEM (NST * STAGE_BYTES)               // 96 KB

__device__ __forceinline__ uint32_t smem_u32(const void* p) {
    uint32_t a;
    asm("{ .reg .u64 t; cvta.to.shared.u64 t, %1; cvt.u32.u64 %0, t; }"
        : "=r"(a) : "l"(p));
    return a;
}
// SW128: 16B granule g (0..7) within 128B row -> g ^ (row & 7).
__device__ __forceinline__ uint32_t sw_off(int row, int g) {
    return (uint32_t)(row * 128 + ((g ^ (row & 7)) << 4));
}
__device__ __forceinline__ void cp16(uint32_t s, const void* gp) {
    asm volatile("cp.async.cg.shared.global [%0], [%1], 16;"
                 :: "r"(s), "l"(gp) : "memory");
}
__device__ __forceinline__ void ldm4(uint32_t* r, uint32_t a) {
    asm volatile("ldmatrix.sync.aligned.m8n8.x4.shared.b16 {%0,%1,%2,%3}, [%4];"
                 : "=r"(r[0]), "=r"(r[1]), "=r"(r[2]), "=r"(r[3]) : "r"(a));
}
__device__ __forceinline__ void mma_bf16(float* c, const uint32_t* a,
                                         const uint32_t* b) {
    asm volatile(
        "mma.sync.aligned.m16n8k16.row.col.f32.bf16.bf16.f32 "
        "{%0,%1,%2,%3}, {%4,%5,%6,%7}, {%8,%9}, {%0,%1,%2,%3};"
        : "+f"(c[0]), "+f"(c[1]), "+f"(c[2]), "+f"(c[3])
        : "r"(a[0]), "r"(a[1]), "r"(a[2]), "r"(a[3]), "r"(b[0]), "r"(b[1]));
}
__device__ __forceinline__ void mma_e4m3(float* c, const uint32_t* a,
                                         const uint32_t* b) {
    asm volatile(
        "mma.sync.aligned.m16n8k32.row.col.f32.e4m3.e4m3.f32 "
        "{%0,%1,%2,%3}, {%4,%5,%6,%7}, {%8,%9}, {%0,%1,%2,%3};"
        : "+f"(c[0]), "+f"(c[1]), "+f"(c[2]), "+f"(c[3])
        : "r"(a[0]), "r"(a[1]), "r"(a[2]), "r"(a[3]), "r"(b[0]), "r"(b[1]));
}

__global__ __launch_bounds__(GTHREADS, 2)
void gemm_mma(const float* __restrict__ bias, float* __restrict__ C) {
    extern __shared__ char smem[];
    const uint32_t sbase = smem_u32(smem);
    const int tid = threadIdx.x;
    const int bm = blockIdx.y * BM, bn = blockIdx.x * BN;

    // cp.async mapping: granule gq (0..7), base row r0 (0..15), 8 rows/oprnd
    const int gq = tid & 7, r0 = tid >> 3;

    // warp fragment mapping: 2x2 grid of 64x64 warp tiles
    const int wid = tid >> 5, lane = tid & 31;
    const int wm = wid >> 1, wn = wid & 1;
    const int a_row_l = lane & 15;
    const int a_g_l   = lane >> 4;
    const int b_row_l = (lane & 7) + ((lane >> 4) << 3);
    const int b_g_l   = (lane >> 3) & 1;

    float acc[4][8][4];
#pragma unroll
    for (int i = 0; i < 4; ++i)
#pragma unroll
        for (int j = 0; j < 8; ++j)
#pragma unroll
            for (int v = 0; v < 4; ++v) acc[i][j][v] = 0.0f;

    auto load_tile = [&](int slot, int kt) {
        const char* Ab; const char* Bb; size_t rstride; int kb;
        if (kt < 32) {
            Ab = (const char*)g_xh;  Bb = (const char*)g_wh;
            rstride = 4096; kb = kt * 128;
        } else if (kt < 48) {
            Ab = (const char*)g_xh8; Bb = (const char*)g_wl8;
            rstride = 2048; kb = (kt - 32) * 128;
        } else {
            Ab = (const char*)g_xl8; Bb = (const char*)g_wh8;
            rstride = 2048; kb = (kt - 48) * 128;
        }
        const char* ga = Ab + (size_t)(bm + r0) * rstride + kb + gq * 16;
        const char* gb = Bb + (size_t)(bn + r0) * rstride + kb + gq * 16;
        const uint32_t sa = sbase + slot * STAGE_BYTES;
        const uint32_t sb = sa + TILE_A_BYTES;
#pragma unroll
        for (int rr = 0; rr < 8; ++rr) {
            cp16(sa + sw_off(r0 + rr * 16, gq), ga + (size_t)(rr * 16) * rstride);
            cp16(sb + sw_off(r0 + rr * 16, gq), gb + (size_t)(rr * 16) * rstride);
        }
    };

    // prologue: fill NST-1 stages
#pragma unroll
    for (int s = 0; s < NST - 1; ++s) {
        load_tile(s, s);
        asm volatile("cp.async.commit_group;" ::: "memory");
    }

    // main loop
    for (int kt = 0; kt < KTOT; ++kt) {
        asm volatile("cp.async.wait_group %0;" :: "n"(NST - 2) : "memory");
        __syncthreads();

        const int nxt = kt + NST - 1;
        if (nxt < KTOT) load_tile(nxt % NST, nxt);
        asm volatile("cp.async.commit_group;" ::: "memory");

        const uint32_t sa = sbase + (kt % NST) * STAGE_BYTES;
        const uint32_t sb = sa + TILE_A_BYTES;
        const bool is8 = (kt >= 32);

        // 4 steps x 32 bytes of K per step; byte-level fragment layout is
        // identical for bf16-k16 and fp8-k32, so the loads are shared.
#pragma unroll
        for (int st = 0; st < 4; ++st) {
            uint32_t afr[4][4], bfr[4][4];
            const int gA = st * 2 + a_g_l;
#pragma unroll
            for (int mi = 0; mi < 4; ++mi)
                ldm4(afr[mi], sa + sw_off(wm * 64 + mi * 16 + a_row_l, gA));
            const int gB = st * 2 + b_g_l;
#pragma unroll
            for (int nj = 0; nj < 4; ++nj)
                ldm4(bfr[nj], sb + sw_off(wn * 64 + nj * 16 + b_row_l, gB));
            if (!is8) {
#pragma unroll
                for (int mi = 0; mi < 4; ++mi)
#pragma unroll
                    for (int ni = 0; ni < 8; ++ni)
                        mma_bf16(acc[mi][ni], afr[mi], &bfr[ni >> 1][(ni & 1) * 2]);
            } else {
#pragma unroll
                for (int mi = 0; mi < 4; ++mi)
#pragma unroll
                    for (int ni = 0; ni < 8; ++ni)
                        mma_e4m3(acc[mi][ni], afr[mi], &bfr[ni >> 1][(ni & 1) * 2]);
            }
        }
    }

    // epilogue: m16n8 c-frag rows lane>>2 / +8, cols (lane&3)*2
#pragma unroll
    for (int mi = 0; mi < 4; ++mi) {
        const int r_lo = bm + wm * 64 + mi * 16 + (lane >> 2);
#pragma unroll
        for (int ni = 0; ni < 8; ++ni) {
            const int c0 = bn + wn * 64 + ni * 8 + (lane & 3) * 2;
            const float b0 = bias[c0], b1 = bias[c0 + 1];
            float2 v0 = make_float2(acc[mi][ni][0] + b0, acc[mi][ni][1] + b1);
            float2 v1 = make_float2(acc[mi][ni][2] + b0, acc[mi][ni][3] + b1);
            *reinterpret_cast<float2*>(C + (size_t)r_lo * ODIM + c0) = v0;
            *reinterpret_cast<float2*>(C + (size_t)(r_lo + 8) * ODIM + c0) = v1;
        }
    }
}

// ===========================================================================
// Host launch: three ordered kernel launches, graph-capturable, no allocs.
// ===========================================================================
extern "C" void kernel_launch(void* const* d_in, const int* in_sizes, int n_in,
                              void* d_out, int out_size) {
    const float* x    = (const float*)d_in[0];   // [4,1024,2048]
    const float* w    = (const float*)d_in[1];   // [2048,2048]
    const float* cb   = (const float*)d_in[2];   // [256,8]
    const float* rs   = (const float*)d_in[3];   // [2048,1]
    const float* bias = (const float*)d_in[4];   // [2048]
    float* out = (float*)d_out;                  // [4,1024,2048]

    pq_quant_kernel<<<NGROUPS / 256, 256>>>(w, cb, rs);
    xsplit_kernel<<<(MDIM * IDIM / 4) / 256, 256>>>(x);

    cudaFuncSetAttribute(gemm_mma,
                         cudaFuncAttributeMaxDynamicSharedMemorySize, GEMM_SMEM);
    dim3 grid(ODIM / BN, MDIM / BM);             // (16, 32) = 512 CTAs
    gemm_mma<<<grid, GTHREADS, GEMM_SMEM>>>(bias, out);
}

// round 11
// speedup vs baseline: 2.1390x; 2.1390x over previous
#include <cuda_runtime.h>
#include <cuda_fp16.h>
#include <cstdint>

// ===========================================================================
// PQLinear: out = x @ wq.T + bias (wq = PQ-dequantized weight).
//  K1: pq_quant (scalar fp32 argmin, byte-identical math to the verified
//      R5/R7/R9 kernel) -> wq as fp16
//  K2: xcvt -> x as fp16
//  K3: single-pass fp16 mma.sync GEMM (fp32 accumulate), K = 2048.
//      Statistical L2 error ~2.8e-4 (fp16 operand rounding), gate is 1e-3.
// Pipeline/swizzle/fragment code identical to the R9-verified GEMM.
// ===========================================================================

#define ODIM 2048
#define IDIM 2048
#define MDIM 4096
#define KCB  256
#define NGROUPS ((ODIM * IDIM) / 8)     // 524288
#define GPR_SHIFT 8                     // groups per weight row

__device__ __align__(16) __half g_w16[ODIM * IDIM];
__device__ __align__(16) __half g_x16[MDIM * IDIM];

// ===========================================================================
// Kernel 1: PQ quantize (argmin math byte-identical to verified kernel).
// ===========================================================================
__global__ __launch_bounds__(256)
void pq_quant_kernel(const float* __restrict__ w,
                     const float* __restrict__ cb,
                     const float* __restrict__ rs) {
    __shared__ float4 s_cb[KCB * 2];
    __shared__ float  s_cn[KCB];

    const int tid = threadIdx.x;
    const float4* cb4 = reinterpret_cast<const float4*>(cb);
    for (int i = tid; i < KCB * 2; i += 256) s_cb[i] = cb4[i];
    __syncthreads();
    for (int i = tid; i < KCB; i += 256) {
        float4 a = s_cb[2 * i], b = s_cb[2 * i + 1];
        s_cn[i] = a.x * a.x + a.y * a.y + a.z * a.z + a.w * a.w +
                  b.x * b.x + b.y * b.y + b.z * b.z + b.w * b.w;
    }
    __syncthreads();

    const int g = blockIdx.x * 256 + tid;
    const int row = g >> GPR_SHIFT;
    const float scale = rs[row];

    const float4* w4 = reinterpret_cast<const float4*>(w);
    float4 w0 = w4[2 * g], w1 = w4[2 * g + 1];
    float gv0 = w0.x / scale, gv1 = w0.y / scale, gv2 = w0.z / scale, gv3 = w0.w / scale;
    float gv4 = w1.x / scale, gv5 = w1.y / scale, gv6 = w1.z / scale, gv7 = w1.w / scale;

    float best = 3.402823466e38f;
    int bi = 0;
#pragma unroll 8
    for (int k = 0; k < KCB; ++k) {
        float4 c0 = s_cb[2 * k], c1 = s_cb[2 * k + 1];
        float dot = gv0 * c0.x;
        dot = fmaf(gv1, c0.y, dot);
        dot = fmaf(gv2, c0.z, dot);
        dot = fmaf(gv3, c0.w, dot);
        dot = fmaf(gv4, c1.x, dot);
        dot = fmaf(gv5, c1.y, dot);
        dot = fmaf(gv6, c1.z, dot);
        dot = fmaf(gv7, c1.w, dot);
        float d = fmaf(-2.0f, dot, s_cn[k]);
        if (d < best) { best = d; bi = k; }       // strict <: first index wins
    }

    float4 q0 = s_cb[2 * bi], q1 = s_cb[2 * bi + 1];
    union H8 { __half h[8]; uint4 u; } hh;
    hh.h[0] = __float2half(q0.x * scale);
    hh.h[1] = __float2half(q0.y * scale);
    hh.h[2] = __float2half(q0.z * scale);
    hh.h[3] = __float2half(q0.w * scale);
    hh.h[4] = __float2half(q1.x * scale);
    hh.h[5] = __float2half(q1.y * scale);
    hh.h[6] = __float2half(q1.z * scale);
    hh.h[7] = __float2half(q1.w * scale);
    reinterpret_cast<uint4*>(g_w16)[g] = hh.u;
}

// ===========================================================================
// Kernel 2: convert x to fp16. One thread = 8 floats -> 16B store.
// ===========================================================================
__global__ __launch_bounds__(256)
void xcvt_kernel(const float* __restrict__ x) {
    const int i = blockIdx.x * 256 + threadIdx.x;     // 8-float chunk index
    float4 a = reinterpret_cast<const float4*>(x)[2 * i];
    float4 b = reinterpret_cast<const float4*>(x)[2 * i + 1];
    union H8 { __half h[8]; uint4 u; } hh;
    hh.h[0] = __float2half(a.x); hh.h[1] = __float2half(a.y);
    hh.h[2] = __float2half(a.z); hh.h[3] = __float2half(a.w);
    hh.h[4] = __float2half(b.x); hh.h[5] = __float2half(b.y);
    hh.h[6] = __float2half(b.z); hh.h[7] = __float2half(b.w);
    reinterpret_cast<uint4*>(g_x16)[i] = hh.u;
}

// ===========================================================================
// Kernel 3: single-pass fp16 mma.sync GEMM.
//   C[m,n] = sum_k A[m,k]*B[n,k] + bias[n],  A = g_x16, B = g_w16 (K-major)
// BM=BN=128, BK=64, 128 threads (4 warps, 64x64 warp tiles), 3-stage cp.async.
// ===========================================================================
#define BM 128
#define BN 128
#define NST 3
#define KTOT 32                        // 2048 / 64
#define GTHREADS 128
#define TILE_A_BYTES (BM * 128)        // 16 KB (128 bytes per row = 64 halfs)
#define TILE_B_BYTES (BN * 128)
#define STAGE_BYTES (TILE_A_BYTES + TILE_B_BYTES)   // 32 KB
#define GEMM_SMEM (NST * STAGE_BYTES)               // 96 KB

__device__ __forceinline__ uint32_t smem_u32(const void* p) {
    uint32_t a;
    asm("{ .reg .u64 t; cvta.to.shared.u64 t, %1; cvt.u32.u64 %0, t; }"
        : "=r"(a) : "l"(p));
    return a;
}
// SW128: 16B granule g (0..7) within 128B row -> g ^ (row & 7).
__device__ __forceinline__ uint32_t sw_off(int row, int g) {
    return (uint32_t)(row * 128 + ((g ^ (row & 7)) << 4));
}
__device__ __forceinline__ void cp16(uint32_t s, const void* gp) {
    asm volatile("cp.async.cg.shared.global [%0], [%1], 16;"
                 :: "r"(s), "l"(gp) : "memory");
}
__device__ __forceinline__ void ldm4(uint32_t* r, uint32_t a) {
    asm volatile("ldmatrix.sync.aligned.m8n8.x4.shared.b16 {%0,%1,%2,%3}, [%4];"
                 : "=r"(r[0]), "=r"(r[1]), "=r"(r[2]), "=r"(r[3]) : "r"(a));
}
__device__ __forceinline__ void mma_f16(float* c, const uint32_t* a,
                                        const uint32_t* b) {
    asm volatile(
        "mma.sync.aligned.m16n8k16.row.col.f32.f16.f16.f32 "
        "{%0,%1,%2,%3}, {%4,%5,%6,%7}, {%8,%9}, {%0,%1,%2,%3};"
        : "+f"(c[0]), "+f"(c[1]), "+f"(c[2]), "+f"(c[3])
        : "r"(a[0]), "r"(a[1]), "r"(a[2]), "r"(a[3]), "r"(b[0]), "r"(b[1]));
}

__global__ __launch_bounds__(GTHREADS, 2)
void gemm_mma(const float* __restrict__ bias, float* __restrict__ C) {
    extern __shared__ char smem[];
    const uint32_t sbase = smem_u32(smem);
    const int tid = threadIdx.x;
    const int bm = blockIdx.y * BM, bn = blockIdx.x * BN;

    // cp.async mapping: granule gq (0..7), base row r0 (0..15), 8 rows/oprnd
    const int gq = tid & 7, r0 = tid >> 3;

    // warp fragment mapping: 2x2 grid of 64x64 warp tiles
    const int wid = tid >> 5, lane = tid & 31;
    const int wm = wid >> 1, wn = wid & 1;
    const int a_row_l = lane & 15;
    const int a_g_l   = lane >> 4;
    const int b_row_l = (lane & 7) + ((lane >> 4) << 3);
    const int b_g_l   = (lane >> 3) & 1;

    float acc[4][8][4];
#pragma unroll
    for (int i = 0; i < 4; ++i)
#pragma unroll
        for (int j = 0; j < 8; ++j)
#pragma unroll
            for (int v = 0; v < 4; ++v) acc[i][j][v] = 0.0f;

    auto load_tile = [&](int slot, int kt) {
        const int kb = kt * 128;                     // byte offset in row
        const char* ga = (const char*)g_x16 + (size_t)(bm + r0) * 4096 + kb + gq * 16;
        const char* gb = (const char*)g_w16 + (size_t)(bn + r0) * 4096 + kb + gq * 16;
        const uint32_t sa = sbase + slot * STAGE_BYTES;
        const uint32_t sb = sa + TILE_A_BYTES;
#pragma unroll
        for (int rr = 0; rr < 8; ++rr) {
            cp16(sa + sw_off(r0 + rr * 16, gq), ga + (size_t)(rr * 16) * 4096);
            cp16(sb + sw_off(r0 + rr * 16, gq), gb + (size_t)(rr * 16) * 4096);
        }
    };

    // prologue: fill NST-1 stages
#pragma unroll
    for (int s = 0; s < NST - 1; ++s) {
        load_tile(s, s);
        asm volatile("cp.async.commit_group;" ::: "memory");
    }

    // main loop
    for (int kt = 0; kt < KTOT; ++kt) {
        asm volatile("cp.async.wait_group %0;" :: "n"(NST - 2) : "memory");
        __syncthreads();

        const int nxt = kt + NST - 1;
        if (nxt < KTOT) load_tile(nxt % NST, nxt);
        asm volatile("cp.async.commit_group;" ::: "memory");

        const uint32_t sa = sbase + (kt % NST) * STAGE_BYTES;
        const uint32_t sb = sa + TILE_A_BYTES;

#pragma unroll
        for (int st = 0; st < 4; ++st) {             // 4 x 16 halfs of K
            uint32_t afr[4][4], bfr[4][4];
            const int gA = st * 2 + a_g_l;
#pragma unroll
            for (int mi = 0; mi < 4; ++mi)
                ldm4(afr[mi], sa + sw_off(wm * 64 + mi * 16 + a_row_l, gA));
            const int gB = st * 2 + b_g_l;
#pragma unroll
            for (int nj = 0; nj < 4; ++nj)
                ldm4(bfr[nj], sb + sw_off(wn * 64 + nj * 16 + b_row_l, gB));
#pragma unroll
            for (int mi = 0; mi < 4; ++mi)
#pragma unroll
                for (int ni = 0; ni < 8; ++ni)
                    mma_f16(acc[mi][ni], afr[mi], &bfr[ni >> 1][(ni & 1) * 2]);
        }
    }

    // epilogue: m16n8 c-frag rows lane>>2 / +8, cols (lane&3)*2
#pragma unroll
    for (int mi = 0; mi < 4; ++mi) {
        const int r_lo = bm + wm * 64 + mi * 16 + (lane >> 2);
#pragma unroll
        for (int ni = 0; ni < 8; ++ni) {
            const int c0 = bn + wn * 64 + ni * 8 + (lane & 3) * 2;
            const float b0 = bias[c0], b1 = bias[c0 + 1];
            float2 v0 = make_float2(acc[mi][ni][0] + b0, acc[mi][ni][1] + b1);
            float2 v1 = make_float2(acc[mi][ni][2] + b0, acc[mi][ni][3] + b1);
            *reinterpret_cast<float2*>(C + (size_t)r_lo * ODIM + c0) = v0;
            *reinterpret_cast<float2*>(C + (size_t)(r_lo + 8) * ODIM + c0) = v1;
        }
    }
}

// ===========================================================================
// Host launch: three ordered kernel launches, graph-capturable, no allocs.
// ===========================================================================
extern "C" void kernel_launch(void* const* d_in, const int* in_sizes, int n_in,
                              void* d_out, int out_size) {
    const float* x    = (const float*)d_in[0];   // [4,1024,2048]
    const float* w    = (const float*)d_in[1];   // [2048,2048]
    const float* cb   = (const float*)d_in[2];   // [256,8]
    const float* rs   = (const float*)d_in[3];   // [2048,1]
    const float* bias = (const float*)d_in[4];   // [2048]
    float* out = (float*)d_out;                  // [4,1024,2048]

    pq_quant_kernel<<<NGROUPS / 256, 256>>>(w, cb, rs);
    xcvt_kernel<<<(MDIM * IDIM / 8) / 256, 256>>>(x);

    cudaFuncSetAttribute(gemm_mma,
                         cudaFuncAttributeMaxDynamicSharedMemorySize, GEMM_SMEM);
    dim3 grid(ODIM / BN, MDIM / BM);             // (16, 32) = 512 CTAs
    gemm_mma<<<grid, GTHREADS, GEMM_SMEM>>>(bias, out);
}

// round 12
// speedup vs baseline: 2.1421x; 1.0014x over previous
#include <cuda_runtime.h>
#include <cuda_fp16.h>
#include <cstdint>

// ===========================================================================
// PQLinear: out = x @ wq.T + bias (wq = PQ-dequantized weight).
//  K1: pq_quant (scalar fp32 argmin, byte-identical math to the verified
//      R5/R7/R9 kernel) -> wq as fp16
//  K2: xcvt -> x as fp16
//  K3: single-pass fp16 mma.sync GEMM (fp32 accumulate), K = 2048.
//      Statistical L2 error ~2.8e-4 (fp16 operand rounding), gate is 1e-3.
// Pipeline/swizzle/fragment code identical to the R9-verified GEMM.
// ===========================================================================

#define ODIM 2048
#define IDIM 2048
#define MDIM 4096
#define KCB  256
#define NGROUPS ((ODIM * IDIM) / 8)     // 524288
#define GPR_SHIFT 8                     // groups per weight row

__device__ __align__(16) __half g_w16[ODIM * IDIM];
__device__ __align__(16) __half g_x16[MDIM * IDIM];

// ===========================================================================
// Kernel 1: PQ quantize (argmin math byte-identical to verified kernel).
// ===========================================================================
__global__ __launch_bounds__(256)
void pq_quant_kernel(const float* __restrict__ w,
                     const float* __restrict__ cb,
                     const float* __restrict__ rs) {
    __shared__ float4 s_cb[KCB * 2];
    __shared__ float  s_cn[KCB];

    const int tid = threadIdx.x;
    const float4* cb4 = reinterpret_cast<const float4*>(cb);
    for (int i = tid; i < KCB * 2; i += 256) s_cb[i] = cb4[i];
    __syncthreads();
    for (int i = tid; i < KCB; i += 256) {
        float4 a = s_cb[2 * i], b = s_cb[2 * i + 1];
        s_cn[i] = a.x * a.x + a.y * a.y + a.z * a.z + a.w * a.w +
                  b.x * b.x + b.y * b.y + b.z * b.z + b.w * b.w;
    }
    __syncthreads();

    const int g = blockIdx.x * 256 + tid;
    const int row = g >> GPR_SHIFT;
    const float scale = rs[row];

    const float4* w4 = reinterpret_cast<const float4*>(w);
    float4 w0 = w4[2 * g], w1 = w4[2 * g + 1];
    float gv0 = w0.x / scale, gv1 = w0.y / scale, gv2 = w0.z / scale, gv3 = w0.w / scale;
    float gv4 = w1.x / scale, gv5 = w1.y / scale, gv6 = w1.z / scale, gv7 = w1.w / scale;

    float best = 3.402823466e38f;
    int bi = 0;
#pragma unroll 8
    for (int k = 0; k < KCB; ++k) {
        float4 c0 = s_cb[2 * k], c1 = s_cb[2 * k + 1];
        float dot = gv0 * c0.x;
        dot = fmaf(gv1, c0.y, dot);
        dot = fmaf(gv2, c0.z, dot);
        dot = fmaf(gv3, c0.w, dot);
        dot = fmaf(gv4, c1.x, dot);
        dot = fmaf(gv5, c1.y, dot);
        dot = fmaf(gv6, c1.z, dot);
        dot = fmaf(gv7, c1.w, dot);
        float d = fmaf(-2.0f, dot, s_cn[k]);
        if (d < best) { best = d; bi = k; }       // strict <: first index wins
    }

    float4 q0 = s_cb[2 * bi], q1 = s_cb[2 * bi + 1];
    union H8 { __half h[8]; uint4 u; } hh;
    hh.h[0] = __float2half(q0.x * scale);
    hh.h[1] = __float2half(q0.y * scale);
    hh.h[2] = __float2half(q0.z * scale);
    hh.h[3] = __float2half(q0.w * scale);
    hh.h[4] = __float2half(q1.x * scale);
    hh.h[5] = __float2half(q1.y * scale);
    hh.h[6] = __float2half(q1.z * scale);
    hh.h[7] = __float2half(q1.w * scale);
    reinterpret_cast<uint4*>(g_w16)[g] = hh.u;
}

// ===========================================================================
// Kernel 2: convert x to fp16. One thread = 8 floats -> 16B store.
// ===========================================================================
__global__ __launch_bounds__(256)
void xcvt_kernel(const float* __restrict__ x) {
    const int i = blockIdx.x * 256 + threadIdx.x;     // 8-float chunk index
    float4 a = reinterpret_cast<const float4*>(x)[2 * i];
    float4 b = reinterpret_cast<const float4*>(x)[2 * i + 1];
    union H8 { __half h[8]; uint4 u; } hh;
    hh.h[0] = __float2half(a.x); hh.h[1] = __float2half(a.y);
    hh.h[2] = __float2half(a.z); hh.h[3] = __float2half(a.w);
    hh.h[4] = __float2half(b.x); hh.h[5] = __float2half(b.y);
    hh.h[6] = __float2half(b.z); hh.h[7] = __float2half(b.w);
    reinterpret_cast<uint4*>(g_x16)[i] = hh.u;
}

// ===========================================================================
// Kernel 3: single-pass fp16 mma.sync GEMM.
//   C[m,n] = sum_k A[m,k]*B[n,k] + bias[n],  A = g_x16, B = g_w16 (K-major)
// BM=BN=128, BK=64, 128 threads (4 warps, 64x64 warp tiles), 3-stage cp.async.
// ===========================================================================
#define BM 128
#define BN 128
#define NST 3
#define KTOT 32                        // 2048 / 64
#define GTHREADS 128
#define TILE_A_BYTES (BM * 128)        // 16 KB (128 bytes per row = 64 halfs)
#define TILE_B_BYTES (BN * 128)
#define STAGE_BYTES (TILE_A_BYTES + TILE_B_BYTES)   // 32 KB
#define GEMM_SMEM (NST * STAGE_BYTES)               // 96 KB

__device__ __forceinline__ uint32_t smem_u32(const void* p) {
    uint32_t a;
    asm("{ .reg .u64 t; cvta.to.shared.u64 t, %1; cvt.u32.u64 %0, t; }"
        : "=r"(a) : "l"(p));
    return a;
}
// SW128: 16B granule g (0..7) within 128B row -> g ^ (row & 7).
__device__ __forceinline__ uint32_t sw_off(int row, int g) {
    return (uint32_t)(row * 128 + ((g ^ (row & 7)) << 4));
}
__device__ __forceinline__ void cp16(uint32_t s, const void* gp) {
    asm volatile("cp.async.cg.shared.global [%0], [%1], 16;"
                 :: "r"(s), "l"(gp) : "memory");
}
__device__ __forceinline__ void ldm4(uint32_t* r, uint32_t a) {
    asm volatile("ldmatrix.sync.aligned.m8n8.x4.shared.b16 {%0,%1,%2,%3}, [%4];"
                 : "=r"(r[0]), "=r"(r[1]), "=r"(r[2]), "=r"(r[3]) : "r"(a));
}
__device__ __forceinline__ void mma_f16(float* c, const uint32_t* a,
                                        const uint32_t* b) {
    asm volatile(
        "mma.sync.aligned.m16n8k16.row.col.f32.f16.f16.f32 "
        "{%0,%1,%2,%3}, {%4,%5,%6,%7}, {%8,%9}, {%0,%1,%2,%3};"
        : "+f"(c[0]), "+f"(c[1]), "+f"(c[2]), "+f"(c[3])
        : "r"(a[0]), "r"(a[1]), "r"(a[2]), "r"(a[3]), "r"(b[0]), "r"(b[1]));
}

__global__ __launch_bounds__(GTHREADS, 2)
void gemm_mma(const float* __restrict__ bias, float* __restrict__ C) {
    extern __shared__ char smem[];
    const uint32_t sbase = smem_u32(smem);
    const int tid = threadIdx.x;
    const int bm = blockIdx.y * BM, bn = blockIdx.x * BN;

    // cp.async mapping: granule gq (0..7), base row r0 (0..15), 8 rows/oprnd
    const int gq = tid & 7, r0 = tid >> 3;

    // warp fragment mapping: 2x2 grid of 64x64 warp tiles
    const int wid = tid >> 5, lane = tid & 31;
    const int wm = wid >> 1, wn = wid & 1;
    const int a_row_l = lane & 15;
    const int a_g_l   = lane >> 4;
    const int b_row_l = (lane & 7) + ((lane >> 4) << 3);
    const int b_g_l   = (lane >> 3) & 1;

    float acc[4][8][4];
#pragma unroll
    for (int i = 0; i < 4; ++i)
#pragma unroll
        for (int j = 0; j < 8; ++j)
#pragma unroll
            for (int v = 0; v < 4; ++v) acc[i][j][v] = 0.0f;

    auto load_tile = [&](int slot, int kt) {
        const int kb = kt * 128;                     // byte offset in row
        const char* ga = (const char*)g_x16 + (size_t)(bm + r0) * 4096 + kb + gq * 16;
        const char* gb = (const char*)g_w16 + (size_t)(bn + r0) * 4096 + kb + gq * 16;
        const uint32_t sa = sbase + slot * STAGE_BYTES;
        const uint32_t sb = sa + TILE_A_BYTES;
#pragma unroll
        for (int rr = 0; rr < 8; ++rr) {
            cp16(sa + sw_off(r0 + rr * 16, gq), ga + (size_t)(rr * 16) * 4096);
            cp16(sb + sw_off(r0 + rr * 16, gq), gb + (size_t)(rr * 16) * 4096);
        }
    };

    // prologue: fill NST-1 stages
#pragma unroll
    for (int s = 0; s < NST - 1; ++s) {
        load_tile(s, s);
        asm volatile("cp.async.commit_group;" ::: "memory");
    }

    // main loop
    for (int kt = 0; kt < KTOT; ++kt) {
        asm volatile("cp.async.wait_group %0;" :: "n"(NST - 2) : "memory");
        __syncthreads();

        const int nxt = kt + NST - 1;
        if (nxt < KTOT) load_tile(nxt % NST, nxt);
        asm volatile("cp.async.commit_group;" ::: "memory");

        const uint32_t sa = sbase + (kt % NST) * STAGE_BYTES;
        const uint32_t sb = sa + TILE_A_BYTES;

#pragma unroll
        for (int st = 0; st < 4; ++st) {             // 4 x 16 halfs of K
            uint32_t afr[4][4], bfr[4][4];
            const int gA = st * 2 + a_g_l;
#pragma unroll
            for (int mi = 0; mi < 4; ++mi)
                ldm4(afr[mi], sa + sw_off(wm * 64 + mi * 16 + a_row_l, gA));
            const int gB = st * 2 + b_g_l;
#pragma unroll
            for (int nj = 0; nj < 4; ++nj)
                ldm4(bfr[nj], sb + sw_off(wn * 64 + nj * 16 + b_row_l, gB));
#pragma unroll
            for (int mi = 0; mi < 4; ++mi)
#pragma unroll
                for (int ni = 0; ni < 8; ++ni)
                    mma_f16(acc[mi][ni], afr[mi], &bfr[ni >> 1][(ni & 1) * 2]);
        }
    }

    // epilogue: m16n8 c-frag rows lane>>2 / +8, cols (lane&3)*2
#pragma unroll
    for (int mi = 0; mi < 4; ++mi) {
        const int r_lo = bm + wm * 64 + mi * 16 + (lane >> 2);
#pragma unroll
        for (int ni = 0; ni < 8; ++ni) {
            const int c0 = bn + wn * 64 + ni * 8 + (lane & 3) * 2;
            const float b0 = bias[c0], b1 = bias[c0 + 1];
            float2 v0 = make_float2(acc[mi][ni][0] + b0, acc[mi][ni][1] + b1);
            float2 v1 = make_float2(acc[mi][ni][2] + b0, acc[mi][ni][3] + b1);
            *reinterpret_cast<float2*>(C + (size_t)r_lo * ODIM + c0) = v0;
            *reinterpret_cast<float2*>(C + (size_t)(r_lo + 8) * ODIM + c0) = v1;
        }
    }
}

// ===========================================================================
// Host launch: three ordered kernel launches, graph-capturable, no allocs.
// ===========================================================================
extern "C" void kernel_launch(void* const* d_in, const int* in_sizes, int n_in,
                              void* d_out, int out_size) {
    const float* x    = (const float*)d_in[0];   // [4,1024,2048]
    const float* w    = (const float*)d_in[1];   // [2048,2048]
    const float* cb   = (const float*)d_in[2];   // [256,8]
    const float* rs   = (const float*)d_in[3];   // [2048,1]
    const float* bias = (const float*)d_in[4];   // [2048]
    float* out = (float*)d_out;                  // [4,1024,2048]

    pq_quant_kernel<<<NGROUPS / 256, 256>>>(w, cb, rs);
    xcvt_kernel<<<(MDIM * IDIM / 8) / 256, 256>>>(x);

    cudaFuncSetAttribute(gemm_mma,
                         cudaFuncAttributeMaxDynamicSharedMemorySize, GEMM_SMEM);
    dim3 grid(ODIM / BN, MDIM / BM);             // (16, 32) = 512 CTAs
    gemm_mma<<<grid, GTHREADS, GEMM_SMEM>>>(bias, out);
}

// round 13
// speedup vs baseline: 2.2470x; 1.0490x over previous
#include <cuda_runtime.h>
#include <cuda_fp16.h>
#include <cstdint>

// ===========================================================================
// PQLinear: out = x @ wq.T + bias (wq = PQ-dequantized weight).
//  K1 (fused): blocks [0,NQBLK): PQ quantize via f32x2-packed codeword PAIRS
//              (per-lane math bit-identical to the verified scalar argmin);
//              blocks [NQBLK,..): x fp32 -> fp16 convert.
//  K2: single-pass fp16 mma.sync GEMM (fp32 accumulate), K = 2048, with
//      fragment double-buffering. Pipeline/swizzle identical to R11-verified.
// ===========================================================================

#define ODIM 2048
#define IDIM 2048
#define MDIM 4096
#define KCB  256
#define NGROUPS ((ODIM * IDIM) / 8)     // 524288
#define GPR_SHIFT 8                     // groups per weight row
#define NQBLK (NGROUPS / 256)           // 2048 quant blocks
#define NXBLK ((MDIM * IDIM / 8) / 256) // 4096 xcvt blocks

__device__ __align__(16) __half g_w16[ODIM * IDIM];
__device__ __align__(16) __half g_x16[MDIM * IDIM];

// -------------------- f32x2 packed helpers (sm_100+ base PTX) --------------
#define PACK2(out, lo, hi) \
    asm("mov.b64 %0, {%1, %2};" : "=l"(out) : "f"(lo), "f"(hi))
#define UNPACK2(lo, hi, in) \
    asm("mov.b64 {%0, %1}, %2;" : "=f"(lo), "=f"(hi) : "l"(in))
#define MUL2(out, a, b) \
    asm("mul.rn.f32x2 %0, %1, %2;" : "=l"(out) : "l"(a), "l"(b))
#define FMA2(out, a, b, c) \
    asm("fma.rn.f32x2 %0, %1, %2, %3;" : "=l"(out) : "l"(a), "l"(b), "l"(c))

// ===========================================================================
// Kernel 1: fused PQ quantize (codeword-pair f32x2) + x convert.
// Lane 0 of each f32x2 handles codeword 2p, lane 1 handles 2p+1; the dot
// chain (mul, 7 fma, fma(-2,dot,cn)) is per-lane IEEE rn — identical to the
// verified scalar kernel. Compares run d(2p) then d(2p+1) with strict <,
// preserving first-index-wins exactly.
// ===========================================================================
__global__ __launch_bounds__(256)
void prep_kernel(const float* __restrict__ w,
                 const float* __restrict__ cb,
                 const float* __restrict__ rs,
                 const float* __restrict__ x) {
    // s_pair[p*8+j] = (cb[2p][j], cb[2p+1][j]);  s_np[p] = (cn[2p], cn[2p+1])
    __shared__ float2 s_pair[(KCB / 2) * 8];   // 8 KB
    __shared__ float2 s_np[KCB / 2];           // 1 KB

    const int tid = threadIdx.x;

    if (blockIdx.x >= NQBLK) {
        // ---------------- xcvt path: 8 floats per thread ----------------
        const int i = (int)(blockIdx.x - NQBLK) * 256 + tid;  // 8-float chunk
        float4 a = reinterpret_cast<const float4*>(x)[2 * i];
        float4 b = reinterpret_cast<const float4*>(x)[2 * i + 1];
        union H8 { __half h[8]; uint4 u; } hh;
        hh.h[0] = __float2half(a.x); hh.h[1] = __float2half(a.y);
        hh.h[2] = __float2half(a.z); hh.h[3] = __float2half(a.w);
        hh.h[4] = __float2half(b.x); hh.h[5] = __float2half(b.y);
        hh.h[6] = __float2half(b.z); hh.h[7] = __float2half(b.w);
        reinterpret_cast<uint4*>(g_x16)[i] = hh.u;
        return;
    }

    // ---- build pair-packed codebook (one codeword per thread; setup-only)
    {
        const float4* cb4 = reinterpret_cast<const float4*>(cb);
        float4 a = cb4[2 * tid], b = cb4[2 * tid + 1];
        float* base = reinterpret_cast<float*>(s_pair) +
                      (tid >> 1) * 16 + (tid & 1);
        base[0]  = a.x; base[2]  = a.y; base[4]  = a.z; base[6]  = a.w;
        base[8]  = b.x; base[10] = b.y; base[12] = b.z; base[14] = b.w;
        float cn = a.x * a.x + a.y * a.y + a.z * a.z + a.w * a.w +
                   b.x * b.x + b.y * b.y + b.z * b.z + b.w * b.w;
        reinterpret_cast<float*>(s_np)[tid] =
            0.0f;  // placeholder init (overwritten below, keeps compiler calm)
        reinterpret_cast<float*>(s_np)[(tid >> 1) * 2 + (tid & 1)] = cn;
    }
    __syncthreads();

    const int g = blockIdx.x * 256 + tid;
    const int row = g >> GPR_SHIFT;
    const float scale = rs[row];

    const float4* w4 = reinterpret_cast<const float4*>(w);
    float4 w0 = w4[2 * g], w1 = w4[2 * g + 1];
    float gv[8] = {w0.x / scale, w0.y / scale, w0.z / scale, w0.w / scale,
                   w1.x / scale, w1.y / scale, w1.z / scale, w1.w / scale};

    unsigned long long pj[8], neg2;
#pragma unroll
    for (int j = 0; j < 8; ++j) PACK2(pj[j], gv[j], gv[j]);
    PACK2(neg2, -2.0f, -2.0f);

    float best = 3.402823466e38f;
    int bi = 0;
    const ulonglong2* cbp = reinterpret_cast<const ulonglong2*>(s_pair);
    const unsigned long long* cnp =
        reinterpret_cast<const unsigned long long*>(s_np);

#pragma unroll 4
    for (int p = 0; p < KCB / 2; ++p) {
        ulonglong2 cA = cbp[4 * p],     cB = cbp[4 * p + 1];
        ulonglong2 cC = cbp[4 * p + 2], cD = cbp[4 * p + 3];
        unsigned long long dot2, d2;
        MUL2(dot2, pj[0], cA.x);
        FMA2(dot2, pj[1], cA.y, dot2);
        FMA2(dot2, pj[2], cB.x, dot2);
        FMA2(dot2, pj[3], cB.y, dot2);
        FMA2(dot2, pj[4], cC.x, dot2);
        FMA2(dot2, pj[5], cC.y, dot2);
        FMA2(dot2, pj[6], cD.x, dot2);
        FMA2(dot2, pj[7], cD.y, dot2);
        FMA2(d2, neg2, dot2, cnp[p]);
        float d0, d1;
        UNPACK2(d0, d1, d2);
        if (d0 < best) { best = d0; bi = 2 * p; }       // k = 2p first
        if (d1 < best) { best = d1; bi = 2 * p + 1; }   // then k = 2p+1
    }

    // decode from pair-packed smem: cb[bi][j] = lane (bi&1) of s_pair[(bi>>1)*8+j]
    const float* crow = reinterpret_cast<const float*>(s_pair) +
                        (bi >> 1) * 16 + (bi & 1);
    union H8 { __half h[8]; uint4 u; } hh;
#pragma unroll
    for (int j = 0; j < 8; ++j)
        hh.h[j] = __float2half(crow[2 * j] * scale);
    reinterpret_cast<uint4*>(g_w16)[g] = hh.u;
}

// ===========================================================================
// Kernel 2: single-pass fp16 mma.sync GEMM with fragment double-buffering.
//   C[m,n] = sum_k A[m,k]*B[n,k] + bias[n],  A = g_x16, B = g_w16 (K-major)
// BM=BN=128, BK=64, 128 threads (4 warps, 64x64 warp tiles), 3-stage cp.async.
// ===========================================================================
#define BM 128
#define BN 128
#define NST 3
#define KTOT 32                        // 2048 / 64
#define GTHREADS 128
#define TILE_A_BYTES (BM * 128)        // 16 KB (128 bytes per row = 64 halfs)
#define TILE_B_BYTES (BN * 128)
#define STAGE_BYTES (TILE_A_BYTES + TILE_B_BYTES)   // 32 KB
#define GEMM_SMEM (NST * STAGE_BYTES)               // 96 KB

__device__ __forceinline__ uint32_t smem_u32(const void* p) {
    uint32_t a;
    asm("{ .reg .u64 t; cvta.to.shared.u64 t, %1; cvt.u32.u64 %0, t; }"
        : "=r"(a) : "l"(p));
    return a;
}
// SW128: 16B granule g (0..7) within 128B row -> g ^ (row & 7).
__device__ __forceinline__ uint32_t sw_off(int row, int g) {
    return (uint32_t)(row * 128 + ((g ^ (row & 7)) << 4));
}
__device__ __forceinline__ void cp16(uint32_t s, const void* gp) {
    asm volatile("cp.async.cg.shared.global [%0], [%1], 16;"
                 :: "r"(s), "l"(gp) : "memory");
}
__device__ __forceinline__ void ldm4(uint32_t* r, uint32_t a) {
    asm volatile("ldmatrix.sync.aligned.m8n8.x4.shared.b16 {%0,%1,%2,%3}, [%4];"
                 : "=r"(r[0]), "=r"(r[1]), "=r"(r[2]), "=r"(r[3]) : "r"(a));
}
__device__ __forceinline__ void mma_f16(float* c, const uint32_t* a,
                                        const uint32_t* b) {
    asm volatile(
        "mma.sync.aligned.m16n8k16.row.col.f32.f16.f16.f32 "
        "{%0,%1,%2,%3}, {%4,%5,%6,%7}, {%8,%9}, {%0,%1,%2,%3};"
        : "+f"(c[0]), "+f"(c[1]), "+f"(c[2]), "+f"(c[3])
        : "r"(a[0]), "r"(a[1]), "r"(a[2]), "r"(a[3]), "r"(b[0]), "r"(b[1]));
}

__global__ __launch_bounds__(GTHREADS, 2)
void gemm_mma(const float* __restrict__ bias, float* __restrict__ C) {
    extern __shared__ char smem[];
    const uint32_t sbase = smem_u32(smem);
    const int tid = threadIdx.x;
    const int bm = blockIdx.y * BM, bn = blockIdx.x * BN;

    // cp.async mapping: granule gq (0..7), base row r0 (0..15), 8 rows/oprnd
    const int gq = tid & 7, r0 = tid >> 3;

    // warp fragment mapping: 2x2 grid of 64x64 warp tiles
    const int wid = tid >> 5, lane = tid & 31;
    const int wm = wid >> 1, wn = wid & 1;
    const int a_row_l = lane & 15;
    const int a_g_l   = lane >> 4;
    const int b_row_l = (lane & 7) + ((lane >> 4) << 3);
    const int b_g_l   = (lane >> 3) & 1;

    float acc[4][8][4];
#pragma unroll
    for (int i = 0; i < 4; ++i)
#pragma unroll
        for (int j = 0; j < 8; ++j)
#pragma unroll
            for (int v = 0; v < 4; ++v) acc[i][j][v] = 0.0f;

    auto load_tile = [&](int slot, int kt) {
        const int kb = kt * 128;                     // byte offset in row
        const char* ga = (const char*)g_x16 + (size_t)(bm + r0) * 4096 + kb + gq * 16;
        const char* gb = (const char*)g_w16 + (size_t)(bn + r0) * 4096 + kb + gq * 16;
        const uint32_t sa = sbase + slot * STAGE_BYTES;
        const uint32_t sb = sa + TILE_A_BYTES;
#pragma unroll
        for (int rr = 0; rr < 8; ++rr) {
            cp16(sa + sw_off(r0 + rr * 16, gq), ga + (size_t)(rr * 16) * 4096);
            cp16(sb + sw_off(r0 + rr * 16, gq), gb + (size_t)(rr * 16) * 4096);
        }
    };

    auto ldfrags = [&](uint32_t sa, uint32_t sb, int st,
                       uint32_t (*afr)[4], uint32_t (*bfr)[4]) {
        const int gA = st * 2 + a_g_l;
#pragma unroll
        for (int mi = 0; mi < 4; ++mi)
            ldm4(afr[mi], sa + sw_off(wm * 64 + mi * 16 + a_row_l, gA));
        const int gB = st * 2 + b_g_l;
#pragma unroll
        for (int nj = 0; nj < 4; ++nj)
            ldm4(bfr[nj], sb + sw_off(wn * 64 + nj * 16 + b_row_l, gB));
    };

    // prologue: fill NST-1 stages
#pragma unroll
    for (int s = 0; s < NST - 1; ++s) {
        load_tile(s, s);
        asm volatile("cp.async.commit_group;" ::: "memory");
    }

    // main loop
    for (int kt = 0; kt < KTOT; ++kt) {
        asm volatile("cp.async.wait_group %0;" :: "n"(NST - 2) : "memory");
        __syncthreads();

        const int nxt = kt + NST - 1;
        if (nxt < KTOT) load_tile(nxt % NST, nxt);
        asm volatile("cp.async.commit_group;" ::: "memory");

        const uint32_t sa = sbase + (kt % NST) * STAGE_BYTES;
        const uint32_t sb = sa + TILE_A_BYTES;

        // double-buffered fragments: ldsm for st+1 under the HMMA of st
        uint32_t afr[2][4][4], bfr[2][4][4];
        ldfrags(sa, sb, 0, afr[0], bfr[0]);
#pragma unroll
        for (int st = 0; st < 4; ++st) {             // 4 x 16 halfs of K
            const int cur = st & 1;
            if (st < 3) ldfrags(sa, sb, st + 1, afr[cur ^ 1], bfr[cur ^ 1]);
#pragma unroll
            for (int mi = 0; mi < 4; ++mi)
#pragma unroll
                for (int ni = 0; ni < 8; ++ni)
                    mma_f16(acc[mi][ni], afr[cur][mi],
                            &bfr[cur][ni >> 1][(ni & 1) * 2]);
        }
    }

    // epilogue: m16n8 c-frag rows lane>>2 / +8, cols (lane&3)*2
#pragma unroll
    for (int mi = 0; mi < 4; ++mi) {
        const int r_lo = bm + wm * 64 + mi * 16 + (lane >> 2);
#pragma unroll
        for (int ni = 0; ni < 8; ++ni) {
            const int c0 = bn + wn * 64 + ni * 8 + (lane & 3) * 2;
            const float b0 = bias[c0], b1 = bias[c0 + 1];
            float2 v0 = make_float2(acc[mi][ni][0] + b0, acc[mi][ni][1] + b1);
            float2 v1 = make_float2(acc[mi][ni][2] + b0, acc[mi][ni][3] + b1);
            *reinterpret_cast<float2*>(C + (size_t)r_lo * ODIM + c0) = v0;
            *reinterpret_cast<float2*>(C + (size_t)(r_lo + 8) * ODIM + c0) = v1;
        }
    }
}

// ===========================================================================
// Host launch: two ordered kernel launches, graph-capturable, no allocs.
// ===========================================================================
extern "C" void kernel_launch(void* const* d_in, const int* in_sizes, int n_in,
                              void* d_out, int out_size) {
    const float* x    = (const float*)d_in[0];   // [4,1024,2048]
    const float* w    = (const float*)d_in[1];   // [2048,2048]
    const float* cb   = (const float*)d_in[2];   // [256,8]
    const float* rs   = (const float*)d_in[3];   // [2048,1]
    const float* bias = (const float*)d_in[4];   // [2048]
    float* out = (float*)d_out;                  // [4,1024,2048]

    prep_kernel<<<NQBLK + NXBLK, 256>>>(w, cb, rs, x);

    cudaFuncSetAttribute(gemm_mma,
                         cudaFuncAttributeMaxDynamicSharedMemorySize, GEMM_SMEM);
    dim3 grid(ODIM / BN, MDIM / BM);             // (16, 32) = 512 CTAs
    gemm_mma<<<grid, GTHREADS, GEMM_SMEM>>>(bias, out);
}

// round 16
// speedup vs baseline: 2.2752x; 1.0125x over previous
#include <cuda_runtime.h>
#include <cuda_fp16.h>
#include <cstdint>

// ===========================================================================
// PQLinear: out = x @ wq.T + bias (wq = PQ-dequantized weight).
//  K1 (fused): quant (f32x2 codeword-pair argmin, verified) + x->fp16.
//  K2: single-pass fp16 mma.sync GEMM, K=2048, with a per-stage mbarrier
//      producer/consumer pipeline (no __syncthreads / wait_group in the main
//      loop). R14 deadlock fixed: cp.async.mbarrier.arrive now uses .noinc
//      (the non-noinc form pre-increments the pending count -> never phases).
// ===========================================================================

#define ODIM 2048
#define IDIM 2048
#define MDIM 4096
#define KCB  256
#define NGROUPS ((ODIM * IDIM) / 8)     // 524288
#define GPR_SHIFT 8                     // groups per weight row
#define NQBLK (NGROUPS / 256)           // 2048 quant blocks
#define NXBLK ((MDIM * IDIM / 8) / 256) // 4096 xcvt blocks

__device__ __align__(16) __half g_w16[ODIM * IDIM];
__device__ __align__(16) __half g_x16[MDIM * IDIM];

// -------------------- f32x2 packed helpers (sm_100+ base PTX) --------------
#define PACK2(out, lo, hi) \
    asm("mov.b64 %0, {%1, %2};" : "=l"(out) : "f"(lo), "f"(hi))
#define UNPACK2(lo, hi, in) \
    asm("mov.b64 {%0, %1}, %2;" : "=f"(lo), "=f"(hi) : "l"(in))
#define MUL2(out, a, b) \
    asm("mul.rn.f32x2 %0, %1, %2;" : "=l"(out) : "l"(a), "l"(b))
#define FMA2(out, a, b, c) \
    asm("fma.rn.f32x2 %0, %1, %2, %3;" : "=l"(out) : "l"(a), "l"(b), "l"(c))

// ===========================================================================
// Kernel 1: fused PQ quantize (codeword-pair f32x2) + x convert.
// Byte-identical to the R13-verified kernel.
// ===========================================================================
__global__ __launch_bounds__(256)
void prep_kernel(const float* __restrict__ w,
                 const float* __restrict__ cb,
                 const float* __restrict__ rs,
                 const float* __restrict__ x) {
    __shared__ float2 s_pair[(KCB / 2) * 8];   // 8 KB
    __shared__ float2 s_np[KCB / 2];           // 1 KB

    const int tid = threadIdx.x;

    if (blockIdx.x >= NQBLK) {
        const int i = (int)(blockIdx.x - NQBLK) * 256 + tid;  // 8-float chunk
        float4 a = reinterpret_cast<const float4*>(x)[2 * i];
        float4 b = reinterpret_cast<const float4*>(x)[2 * i + 1];
        union H8 { __half h[8]; uint4 u; } hh;
        hh.h[0] = __float2half(a.x); hh.h[1] = __float2half(a.y);
        hh.h[2] = __float2half(a.z); hh.h[3] = __float2half(a.w);
        hh.h[4] = __float2half(b.x); hh.h[5] = __float2half(b.y);
        hh.h[6] = __float2half(b.z); hh.h[7] = __float2half(b.w);
        reinterpret_cast<uint4*>(g_x16)[i] = hh.u;
        return;
    }

    {
        const float4* cb4 = reinterpret_cast<const float4*>(cb);
        float4 a = cb4[2 * tid], b = cb4[2 * tid + 1];
        float* base = reinterpret_cast<float*>(s_pair) +
                      (tid >> 1) * 16 + (tid & 1);
        base[0]  = a.x; base[2]  = a.y; base[4]  = a.z; base[6]  = a.w;
        base[8]  = b.x; base[10] = b.y; base[12] = b.z; base[14] = b.w;
        float cn = a.x * a.x + a.y * a.y + a.z * a.z + a.w * a.w +
                   b.x * b.x + b.y * b.y + b.z * b.z + b.w * b.w;
        reinterpret_cast<float*>(s_np)[(tid >> 1) * 2 + (tid & 1)] = cn;
    }
    __syncthreads();

    const int g = blockIdx.x * 256 + tid;
    const int row = g >> GPR_SHIFT;
    const float scale = rs[row];

    const float4* w4 = reinterpret_cast<const float4*>(w);
    float4 w0 = w4[2 * g], w1 = w4[2 * g + 1];
    float gv[8] = {w0.x / scale, w0.y / scale, w0.z / scale, w0.w / scale,
                   w1.x / scale, w1.y / scale, w1.z / scale, w1.w / scale};

    unsigned long long pj[8], neg2;
#pragma unroll
    for (int j = 0; j < 8; ++j) PACK2(pj[j], gv[j], gv[j]);
    PACK2(neg2, -2.0f, -2.0f);

    float best = 3.402823466e38f;
    int bi = 0;
    const ulonglong2* cbp = reinterpret_cast<const ulonglong2*>(s_pair);
    const unsigned long long* cnp =
        reinterpret_cast<const unsigned long long*>(s_np);

#pragma unroll 4
    for (int p = 0; p < KCB / 2; ++p) {
        ulonglong2 cA = cbp[4 * p],     cB = cbp[4 * p + 1];
        ulonglong2 cC = cbp[4 * p + 2], cD = cbp[4 * p + 3];
        unsigned long long dot2, d2;
        MUL2(dot2, pj[0], cA.x);
        FMA2(dot2, pj[1], cA.y, dot2);
        FMA2(dot2, pj[2], cB.x, dot2);
        FMA2(dot2, pj[3], cB.y, dot2);
        FMA2(dot2, pj[4], cC.x, dot2);
        FMA2(dot2, pj[5], cC.y, dot2);
        FMA2(dot2, pj[6], cD.x, dot2);
        FMA2(dot2, pj[7], cD.y, dot2);
        FMA2(d2, neg2, dot2, cnp[p]);
        float d0, d1;
        UNPACK2(d0, d1, d2);
        if (d0 < best) { best = d0; bi = 2 * p; }
        if (d1 < best) { best = d1; bi = 2 * p + 1; }
    }

    const float* crow = reinterpret_cast<const float*>(s_pair) +
                        (bi >> 1) * 16 + (bi & 1);
    union H8 { __half h[8]; uint4 u; } hh;
#pragma unroll
    for (int j = 0; j < 8; ++j)
        hh.h[j] = __float2half(crow[2 * j] * scale);
    reinterpret_cast<uint4*>(g_w16)[g] = hh.u;
}

// ===========================================================================
// Kernel 2: fp16 mma.sync GEMM with mbarrier producer/consumer pipeline.
//   C[m,n] = sum_k A[m,k]*B[n,k] + bias[n],  A = g_x16, B = g_w16 (K-major)
// BM=BN=128, BK=64, 128 threads (4 warps, 64x64 warp tiles), 3 stages.
// smem: [0..24) full mbars, [24..48) empty mbars, [128..) stages.
// ===========================================================================
#define BM 128
#define BN 128
#define NST 3
#define KTOT 32                        // 2048 / 64
#define GTHREADS 128
#define TILE_A_BYTES (BM * 128)        // 16 KB
#define TILE_B_BYTES (BN * 128)
#define STAGE_BYTES (TILE_A_BYTES + TILE_B_BYTES)   // 32 KB
#define OFF_STAGES 128
#define GEMM_SMEM (OFF_STAGES + NST * STAGE_BYTES)  // 98432

__device__ __forceinline__ uint32_t smem_u32(const void* p) {
    uint32_t a;
    asm("{ .reg .u64 t; cvta.to.shared.u64 t, %1; cvt.u32.u64 %0, t; }"
        : "=r"(a) : "l"(p));
    return a;
}
__device__ __forceinline__ uint32_t sw_off(int row, int g) {
    return (uint32_t)(row * 128 + ((g ^ (row & 7)) << 4));
}
__device__ __forceinline__ void cp16(uint32_t s, const void* gp) {
    asm volatile("cp.async.cg.shared.global [%0], [%1], 16;"
                 :: "r"(s), "l"(gp) : "memory");
}
__device__ __forceinline__ void ldm4(uint32_t* r, uint32_t a) {
    asm volatile("ldmatrix.sync.aligned.m8n8.x4.shared.b16 {%0,%1,%2,%3}, [%4];"
                 : "=r"(r[0]), "=r"(r[1]), "=r"(r[2]), "=r"(r[3]) : "r"(a));
}
__device__ __forceinline__ void mma_f16(float* c, const uint32_t* a,
                                        const uint32_t* b) {
    asm volatile(
        "mma.sync.aligned.m16n8k16.row.col.f32.f16.f16.f32 "
        "{%0,%1,%2,%3}, {%4,%5,%6,%7}, {%8,%9}, {%0,%1,%2,%3};"
        : "+f"(c[0]), "+f"(c[1]), "+f"(c[2]), "+f"(c[3])
        : "r"(a[0]), "r"(a[1]), "r"(a[2]), "r"(a[3]), "r"(b[0]), "r"(b[1]));
}

#define MBAR_INIT(addr, cnt) \
    asm volatile("mbarrier.init.shared.b64 [%0], %1;" \
                 :: "r"(addr), "r"(cnt) : "memory")
#define MBAR_ARRIVE(addr) \
    asm volatile("mbarrier.arrive.shared.b64 _, [%0];" \
                 :: "r"(addr) : "memory")
// .noinc: this thread contributes exactly ONE arrival, fired when its prior
// cp.asyncs complete. (Non-noinc pre-increments pending count -> deadlock.)
#define CPASYNC_MBAR_ARRIVE(addr) \
    asm volatile("cp.async.mbarrier.arrive.noinc.shared.b64 [%0];" \
                 :: "r"(addr) : "memory")
#define MBAR_WAIT(addr, ph) do {                                              \
    uint32_t _m = (addr), _p = (uint32_t)(ph), _d;                            \
    asm volatile("{\n\t.reg .pred p;\n\t"                                     \
        "mbarrier.try_wait.parity.acquire.cta.shared::cta.b64 p, [%1], %2;\n\t" \
        "selp.b32 %0, 1, 0, p;\n\t}" : "=r"(_d) : "r"(_m), "r"(_p) : "memory"); \
    if (!_d) {                                                                \
        asm volatile("{\n\t.reg .pred P1;\n\t"                                \
            "W%=:\n\t"                                                        \
            "mbarrier.try_wait.parity.acquire.cta.shared::cta.b64 P1, [%0], %1, 0x989680;\n\t" \
            "@P1 bra.uni D%=;\n\t bra.uni W%=;\n\t D%=:\n\t}"                 \
            :: "r"(_m), "r"(_p) : "memory");                                  \
    } } while (0)

__global__ __launch_bounds__(GTHREADS, 2)
void gemm_mma(const float* __restrict__ bias, float* __restrict__ C) {
    extern __shared__ char smem[];
    const uint32_t sbase = smem_u32(smem);
    const int tid = threadIdx.x;
    const int bm = blockIdx.y * BM, bn = blockIdx.x * BN;

    const uint32_t mb_full  = sbase;        // 3 x 8B
    const uint32_t mb_empty = sbase + 24;   // 3 x 8B
    const uint32_t stg0     = sbase + OFF_STAGES;

    if (tid == 0) {
        for (int s = 0; s < NST; ++s) {
            MBAR_INIT(mb_full  + s * 8, GTHREADS);
            MBAR_INIT(mb_empty + s * 8, GTHREADS);
        }
    }
    __syncthreads();

    const int gq = tid & 7, r0 = tid >> 3;
    const int wid = tid >> 5, lane = tid & 31;
    const int wm = wid >> 1, wn = wid & 1;
    const int a_row_l = lane & 15;
    const int a_g_l   = lane >> 4;
    const int b_row_l = (lane & 7) + ((lane >> 4) << 3);
    const int b_g_l   = (lane >> 3) & 1;

    float acc[4][8][4];
#pragma unroll
    for (int i = 0; i < 4; ++i)
#pragma unroll
        for (int j = 0; j < 8; ++j)
#pragma unroll
            for (int v = 0; v < 4; ++v) acc[i][j][v] = 0.0f;

    auto load_tile = [&](int slot, int kt) {
        const int kb = kt * 128;
        const char* ga = (const char*)g_x16 + (size_t)(bm + r0) * 4096 + kb + gq * 16;
        const char* gb = (const char*)g_w16 + (size_t)(bn + r0) * 4096 + kb + gq * 16;
        const uint32_t sa = stg0 + slot * STAGE_BYTES;
        const uint32_t sb = sa + TILE_A_BYTES;
#pragma unroll
        for (int rr = 0; rr < 8; ++rr) {
            cp16(sa + sw_off(r0 + rr * 16, gq), ga + (size_t)(rr * 16) * 4096);
            cp16(sb + sw_off(r0 + rr * 16, gq), gb + (size_t)(rr * 16) * 4096);
        }
        CPASYNC_MBAR_ARRIVE(mb_full + slot * 8);   // fires when cps complete
    };

    auto ldfrags = [&](uint32_t sa, uint32_t sb, int st,
                       uint32_t (*afr)[4], uint32_t (*bfr)[4]) {
        const int gA = st * 2 + a_g_l;
#pragma unroll
        for (int mi = 0; mi < 4; ++mi)
            ldm4(afr[mi], sa + sw_off(wm * 64 + mi * 16 + a_row_l, gA));
        const int gB = st * 2 + b_g_l;
#pragma unroll
        for (int nj = 0; nj < 4; ++nj)
            ldm4(bfr[nj], sb + sw_off(wn * 64 + nj * 16 + b_row_l, gB));
    };

    // prologue: fill stages 0 and 1 (no empty-wait needed on virgin stages)
    load_tile(0, 0);
    load_tile(1, 1);

    // producer cursor: next slot 2, phase 1 (virgin empty-wait passes)
    int pslot = 2, pphase = 1;
    // consumer cursor: slot 0, phase 0
    int cslot = 0, cphase = 0;

    for (int kt = 0; kt < KTOT; ++kt) {
        // produce kt+2
        if (kt + 2 < KTOT) {
            MBAR_WAIT(mb_empty + pslot * 8, pphase);
            load_tile(pslot, kt + 2);
        }
        if (++pslot == NST) { pslot = 0; pphase ^= 1; }

        // consume kt
        MBAR_WAIT(mb_full + cslot * 8, cphase);
        const uint32_t sa = stg0 + cslot * STAGE_BYTES;
        const uint32_t sb = sa + TILE_A_BYTES;

        uint32_t afr[2][4][4], bfr[2][4][4];
        ldfrags(sa, sb, 0, afr[0], bfr[0]);
#pragma unroll
        for (int st = 0; st < 4; ++st) {
            const int cur = st & 1;
            if (st < 3) ldfrags(sa, sb, st + 1, afr[cur ^ 1], bfr[cur ^ 1]);
#pragma unroll
            for (int mi = 0; mi < 4; ++mi)
#pragma unroll
                for (int ni = 0; ni < 8; ++ni)
                    mma_f16(acc[mi][ni], afr[cur][mi],
                            &bfr[cur][ni >> 1][(ni & 1) * 2]);
        }
        MBAR_ARRIVE(mb_empty + cslot * 8);         // done reading this stage
        if (++cslot == NST) { cslot = 0; cphase ^= 1; }
    }

    // epilogue: m16n8 c-frag rows lane>>2 / +8, cols (lane&3)*2
#pragma unroll
    for (int mi = 0; mi < 4; ++mi) {
        const int r_lo = bm + wm * 64 + mi * 16 + (lane >> 2);
#pragma unroll
        for (int ni = 0; ni < 8; ++ni) {
            const int c0 = bn + wn * 64 + ni * 8 + (lane & 3) * 2;
            const float b0 = bias[c0], b1 = bias[c0 + 1];
            float2 v0 = make_float2(acc[mi][ni][0] + b0, acc[mi][ni][1] + b1);
            float2 v1 = make_float2(acc[mi][ni][2] + b0, acc[mi][ni][3] + b1);
            *reinterpret_cast<float2*>(C + (size_t)r_lo * ODIM + c0) = v0;
            *reinterpret_cast<float2*>(C + (size_t)(r_lo + 8) * ODIM + c0) = v1;
        }
    }
}

// ===========================================================================
// Host launch: two ordered kernel launches, graph-capturable, no allocs.
// ===========================================================================
extern "C" void kernel_launch(void* const* d_in, const int* in_sizes, int n_in,
                              void* d_out, int out_size) {
    const float* x    = (const float*)d_in[0];   // [4,1024,2048]
    const float* w    = (const float*)d_in[1];   // [2048,2048]
    const float* cb   = (const float*)d_in[2];   // [256,8]
    const float* rs   = (const float*)d_in[3];   // [2048,1]
    const float* bias = (const float*)d_in[4];   // [2048]
    float* out = (float*)d_out;                  // [4,1024,2048]

    prep_kernel<<<NQBLK + NXBLK, 256>>>(w, cb, rs, x);

    cudaFuncSetAttribute(gemm_mma,
                         cudaFuncAttributeMaxDynamicSharedMemorySize, GEMM_SMEM);
    dim3 grid(ODIM / BN, MDIM / BM);             // (16, 32) = 512 CTAs
    gemm_mma<<<grid, GTHREADS, GEMM_SMEM>>>(bias, out);
}